// round 13
// baseline (speedup 1.0000x reference)
#include <cuda_runtime.h>
#include <cuda_fp16.h>
#include <math.h>
#include <stdint.h>

#define BB 4
#define TT 2048
#define UU 1024
#define HH 8
#define DD 128
#define BT (BB*TT)

typedef unsigned long long u64;

// Scratch (device globals per harness allocation rules)
static __device__ float  g_Q[BT*UU];                  // 33.5 MB (pre-scaled q)
static __device__ float  g_K[BT*UU];                  // 33.5 MB
static __device__ float  g_V[BT*DD];                  // 4.2 MB
static __device__ float  g_L[BB*HH*TT];               // row sum-exp per (b,h,t)
static __device__ float  g_OP[BT*DD];                 // attn @ v
static __device__ float  g_WT[UU*UU];                 // transposed weight buffer
static __device__ __half g_S[(size_t)BB*HH*TT*TT];    // 268 MB: W = exp(score), fp16

// ===================== mma.sync tf32 helpers (sm_80 path) ===================
__device__ __forceinline__ uint32_t smem_u32(const void* p) {
    uint32_t a;
    asm("{ .reg .u64 t; cvta.to.shared.u64 t, %1; cvt.u32.u64 %0, t; }" : "=r"(a) : "l"(p));
    return a;
}
__device__ __forceinline__ unsigned f2tf(float f) {
    unsigned u; asm("cvt.rna.tf32.f32 %0, %1;" : "=r"(u) : "f"(f)); return u;
}
__device__ __forceinline__ void mma8(float* c, const unsigned* a, const unsigned* b) {
    asm volatile("mma.sync.aligned.m16n8k8.row.col.f32.tf32.tf32.f32 "
        "{%0,%1,%2,%3}, {%4,%5,%6,%7}, {%8,%9}, {%0,%1,%2,%3};"
        : "+f"(c[0]), "+f"(c[1]), "+f"(c[2]), "+f"(c[3])
        : "r"(a[0]), "r"(a[1]), "r"(a[2]), "r"(a[3]), "r"(b[0]), "r"(b[1]));
}
__device__ __forceinline__ void ldsm4(unsigned* r, uint32_t addr) {
    asm volatile("ldmatrix.sync.aligned.m8n8.x4.shared.b16 {%0,%1,%2,%3}, [%4];"
        : "=r"(r[0]), "=r"(r[1]), "=r"(r[2]), "=r"(r[3]) : "r"(addr));
}

// Smem tile layout: [kc][row][12 floats] (8 used + 4 pad = 48B pitch).
// 48B pitch => ldmatrix 8-address phases hit 8 distinct 16B banks.
#define PITCH 12

// A-fragment ldmatrix address offsets (warp rows mrow0..mrow0+15):
//   lane<16: (row = mrow0 + lane,      col 0..3)
//   lane>=16:(row = mrow0 + lane - 16, col 4..7)
__device__ __forceinline__ uint32_t a_addr(uint32_t base, int kc, int mrow0, int lane) {
    int row = mrow0 + (lane & 15);
    int col = (lane >> 4) * 4;
    return base + (uint32_t)((kc * 128 + row) * PITCH + col) * 4u;
}
// B-fragment (x4 covers n-tiles n0 and n0+8):
//   lane 0-7:(n0+l, 0) 8-15:(n0+l-8, 4) 16-23:(n0+8+l-16, 0) 24-31:(n0+8+l-24, 4)
__device__ __forceinline__ uint32_t b_addr(uint32_t base, int kc, int n0, int lane) {
    int row = n0 + (lane & 7) + ((lane >> 4) << 3);
    int col = ((lane >> 3) & 1) * 4;
    return base + (uint32_t)((kc * 128 + row) * PITCH + col) * 4u;
}

// ---------------------------------------------------------------------------
// 32x32 transpose: WT[n][k] = W[k][n]  (UU x UU)
// ---------------------------------------------------------------------------
__global__ void transpose_kernel(const float* __restrict__ W, float* __restrict__ WT)
{
    __shared__ float t[32][33];
    int bx = blockIdx.x * 32, by = blockIdx.y * 32;
    #pragma unroll
    for (int i = 0; i < 32; i += 8)
        t[threadIdx.y + i][threadIdx.x] = W[(size_t)(by + threadIdx.y + i) * UU + bx + threadIdx.x];
    __syncthreads();
    #pragma unroll
    for (int i = 0; i < 32; i += 8)
        WT[(size_t)(bx + threadIdx.y + i) * UU + by + threadIdx.x] = t[threadIdx.x][threadIdx.y + i];
}

// ---------------------------------------------------------------------------
// tf32 mma.sync projection GEMM: C[M,N] = alpha * X[M,K] @ WT[N,K]^T
// Block 128x128, 8 warps (warp tile 16m x 128n), K-chunk 32.
// Grid (N/128, M/128). Dynamic smem: 2 * 4*128*48 = 48 KB.
// ---------------------------------------------------------------------------
__global__ __launch_bounds__(256, 2) void mma_proj_kernel(
    const float* __restrict__ X, const float* __restrict__ WT, float* __restrict__ C,
    float alpha)
{
    extern __shared__ float sm[];
    float* As = sm;                       // [4][128][12]
    float* Bs = sm + 4 * 128 * PITCH;     // [4][128][12]
    const uint32_t as_b = smem_u32(As), bs_b = smem_u32(Bs);

    const int tid = threadIdx.x;
    const int wid = tid >> 5, lane = tid & 31;
    const int n0 = blockIdx.x * 128, m0 = blockIdx.y * 128;
    const int mrow0 = wid * 16;

    float acc[16][4];
    #pragma unroll
    for (int j = 0; j < 16; j++)
        #pragma unroll
        for (int q = 0; q < 4; q++) acc[j][q] = 0.0f;

    for (int kb = 0; kb < UU; kb += 32) {
        // Stage A and B chunks (128 rows x 32 k) as tf32
        #pragma unroll
        for (int it = 0; it < 4; it++) {
            int idx = it * 256 + tid;          // 0..1023 float4s
            int r = idx >> 3;
            int kk = (idx & 7) * 4;
            int kc = kk >> 3, kin = kk & 7;
            float4 va = *(const float4*)(X + (size_t)(m0 + r) * UU + kb + kk);
            uint4 oa = make_uint4(f2tf(va.x), f2tf(va.y), f2tf(va.z), f2tf(va.w));
            *(uint4*)&As[(kc * 128 + r) * PITCH + kin] = oa;
            float4 vb = *(const float4*)(WT + (size_t)(n0 + r) * UU + kb + kk);
            uint4 ob = make_uint4(f2tf(vb.x), f2tf(vb.y), f2tf(vb.z), f2tf(vb.w));
            *(uint4*)&Bs[(kc * 128 + r) * PITCH + kin] = ob;
        }
        __syncthreads();

        #pragma unroll
        for (int kc = 0; kc < 4; kc++) {
            unsigned af[4];
            ldsm4(af, a_addr(as_b, kc, mrow0, lane));
            #pragma unroll
            for (int j = 0; j < 8; j++) {
                unsigned bf[4];
                ldsm4(bf, b_addr(bs_b, kc, j * 16, lane));
                mma8(acc[2 * j],     af, bf);
                mma8(acc[2 * j + 1], af, bf + 2);
            }
        }
        __syncthreads();
    }

    // Epilogue: c0,c1 -> (row=gid, col=j*8+2t, +1); c2,c3 -> row=gid+8
    const int gid = lane >> 2, tig = lane & 3;
    const int r0 = m0 + mrow0 + gid;
    #pragma unroll
    for (int j = 0; j < 16; j++) {
        int cc = n0 + j * 8 + 2 * tig;
        *(float2*)(C + (size_t)r0 * UU + cc) =
            make_float2(alpha * acc[j][0], alpha * acc[j][1]);
        *(float2*)(C + (size_t)(r0 + 8) * UU + cc) =
            make_float2(alpha * acc[j][2], alpha * acc[j][3]);
    }
}

// ---------------------------------------------------------------------------
// tf32 mma.sync score kernel: per (b, h, qt): scores vs all causal s-tiles,
// W = exp(score) -> fp16 g_S, row sums -> g_L.
// Q fragments live in registers (loaded once); K tiles stream through 96 KB smem.
// Grid (TT/128, HH, BB), 256 threads (8 warps x 16 rows).
// ---------------------------------------------------------------------------
__global__ __launch_bounds__(256, 1) void mma_score_kernel()
{
    extern __shared__ float sm[];                 // [16][128][12] = 96 KB
    const uint32_t sm_b = smem_u32(sm);

    const int tid = threadIdx.x;
    const int wid = tid >> 5, lane = tid & 31;
    const int qt = blockIdx.x, h = blockIdx.y, b = blockIdx.z;
    const int mrow0 = wid * 16;
    const int gid = lane >> 2, tig = lane & 3;

    const float* Qsrc  = g_Q + ((size_t)b * TT + (size_t)qt * 128) * UU + h * DD;
    const float* Kbase = g_K + (size_t)b * TT * UU + h * DD;
    __half* Sp = g_S + ((size_t)(b * HH + h) * TT + (size_t)qt * 128) * TT;

    // ---- Stage Q tile (128x128) and hoist fragments to registers ----
    #pragma unroll
    for (int it = 0; it < 16; it++) {
        int idx = it * 256 + tid;            // 0..4095 float4s
        int r = idx >> 5;
        int kk = (idx & 31) * 4;
        int kc = kk >> 3, kin = kk & 7;
        float4 v = *(const float4*)(Qsrc + (size_t)r * UU + kk);
        uint4 o = make_uint4(f2tf(v.x), f2tf(v.y), f2tf(v.z), f2tf(v.w));
        *(uint4*)&sm[(kc * 128 + r) * PITCH + kin] = o;
    }
    __syncthreads();

    unsigned qf[16][4];
    #pragma unroll
    for (int kc = 0; kc < 16; kc++)
        ldsm4(qf[kc], a_addr(sm_b, kc, mrow0, lane));
    __syncthreads();

    const int row0 = mrow0 + gid;            // local rows row0, row0+8
    const int t0 = qt * 128 + row0;
    float lsum0 = 0.0f, lsum1 = 0.0f;

    for (int st = 0; st <= qt; st++) {
        // Stage K tile (128 n x 128 k)
        #pragma unroll
        for (int it = 0; it < 16; it++) {
            int idx = it * 256 + tid;
            int r = idx >> 5;
            int kk = (idx & 31) * 4;
            int kc = kk >> 3, kin = kk & 7;
            float4 v = *(const float4*)(Kbase + (size_t)(st * 128 + r) * UU + kk);
            uint4 o = make_uint4(f2tf(v.x), f2tf(v.y), f2tf(v.z), f2tf(v.w));
            *(uint4*)&sm[(kc * 128 + r) * PITCH + kin] = o;
        }
        __syncthreads();

        float acc[16][4];
        #pragma unroll
        for (int j = 0; j < 16; j++)
            #pragma unroll
            for (int q = 0; q < 4; q++) acc[j][q] = 0.0f;

        #pragma unroll
        for (int kc = 0; kc < 16; kc++) {
            #pragma unroll
            for (int j = 0; j < 8; j++) {
                unsigned bf[4];
                ldsm4(bf, b_addr(sm_b, kc, j * 16, lane));
                mma8(acc[2 * j],     qf[kc], bf);
                mma8(acc[2 * j + 1], qf[kc], bf + 2);
            }
        }

        // Epilogue: mask diag, exp, accumulate l, store fp16
        const bool diag = (st == qt);
        __half* s0 = Sp + (size_t)row0 * TT + st * 128;
        __half* s1 = s0 + (size_t)8 * TT;
        #pragma unroll
        for (int j = 0; j < 16; j++) {
            int cc = j * 8 + 2 * tig;        // col within tile
            float w00 = (diag && (cc     > row0)) ? 0.0f : __expf(acc[j][0]);
            float w01 = (diag && (cc + 1 > row0)) ? 0.0f : __expf(acc[j][1]);
            float w10 = (diag && (cc     > row0 + 8)) ? 0.0f : __expf(acc[j][2]);
            float w11 = (diag && (cc + 1 > row0 + 8)) ? 0.0f : __expf(acc[j][3]);
            lsum0 += w00 + w01;
            lsum1 += w10 + w11;
            __half2 h0 = __floats2half2_rn(w00, w01);
            __half2 h1 = __floats2half2_rn(w10, w11);
            *(__half2*)(s0 + cc) = h0;
            *(__half2*)(s1 + cc) = h1;
        }
        __syncthreads();
    }

    // Row-sum reduce across the 4 lanes of each gid group (xor 1, 2)
    #pragma unroll
    for (int o = 1; o <= 2; o <<= 1) {
        lsum0 += __shfl_xor_sync(0xffffffffu, lsum0, o);
        lsum1 += __shfl_xor_sync(0xffffffffu, lsum1, o);
    }
    if (tig == 0) {
        size_t lb = (size_t)(b * HH + h) * TT;
        g_L[lb + t0]     = lsum0;
        g_L[lb + t0 + 8] = lsum1;
    }
}

// ---------------- f32x2 packed-FMA helpers (Blackwell FFMA2) ----------------
__device__ __forceinline__ u64 ffma2(u64 a, u64 b, u64 c) {
    u64 d;
    asm("fma.rn.f32x2 %0, %1, %2, %3;" : "=l"(d) : "l"(a), "l"(b), "l"(c));
    return d;
}
__device__ __forceinline__ u64 dup2(float x) {
    u64 r;
    asm("mov.b64 %0, {%1, %1};" : "=l"(r) : "f"(x));
    return r;
}
__device__ __forceinline__ float2 u2f(u64 v) {
    float2 f;
    asm("mov.b64 {%0, %1}, %2;" : "=f"(f.x), "=f"(f.y) : "l"(v));
    return f;
}

// ---------------------------------------------------------------------------
// fp32 GEMM with f32x2 math (small stages): C = alpha * A @ B
// ---------------------------------------------------------------------------
__global__ __launch_bounds__(256, 2) void sgemm_kernel(
    const float* __restrict__ A, const float* __restrict__ Bm, float* __restrict__ C,
    int M, int N, int K, float alpha,
    size_t sA, size_t sB, size_t sC, int causalK)
{
    A  += sA * blockIdx.z;
    Bm += sB * blockIdx.z;
    C  += sC * blockIdx.z;

    __shared__ __align__(16) float As[16][132];
    __shared__ __align__(16) float Bs[16][132];

    const int m0 = blockIdx.y * 128;
    const int n0 = blockIdx.x * 128;
    const int tid = threadIdx.x;
    const int ty = tid >> 4;
    const int tx = tid & 15;

    int Keff = causalK ? (int)(blockIdx.y + 1) * 128 : K;
    if (Keff > K) Keff = K;

    u64 acc[8][4];
    #pragma unroll
    for (int i = 0; i < 8; i++)
        #pragma unroll
        for (int j = 0; j < 4; j++) acc[i][j] = 0ull;

    for (int kt = 0; kt < Keff; kt += 16) {
        #pragma unroll
        for (int r = 0; r < 2; r++) {
            int e = tid + r * 256;
            int i = e >> 2, kk = (e & 3) << 2;
            float4 v = *(const float4*)(A + (size_t)(m0 + i) * K + kt + kk);
            As[kk + 0][i] = v.x; As[kk + 1][i] = v.y;
            As[kk + 2][i] = v.z; As[kk + 3][i] = v.w;
        }
        #pragma unroll
        for (int r = 0; r < 2; r++) {
            int e = tid + r * 256;
            int kk = e >> 5, j = (e & 31) << 2;
            *(float4*)&Bs[kk][j] = *(const float4*)(Bm + (size_t)(kt + kk) * N + n0 + j);
        }
        __syncthreads();

        #pragma unroll
        for (int k = 0; k < 16; k++) {
            float4 a0 = *(float4*)&As[k][ty * 8];
            float4 a1 = *(float4*)&As[k][ty * 8 + 4];
            ulonglong2 b0 = *(ulonglong2*)&Bs[k][tx * 8];
            ulonglong2 b1 = *(ulonglong2*)&Bs[k][tx * 8 + 4];
            u64 b[4] = {b0.x, b0.y, b1.x, b1.y};
            float av[8] = {a0.x, a0.y, a0.z, a0.w, a1.x, a1.y, a1.z, a1.w};
            #pragma unroll
            for (int i = 0; i < 8; i++) {
                u64 ad = dup2(av[i]);
                #pragma unroll
                for (int j = 0; j < 4; j++)
                    acc[i][j] = ffma2(ad, b[j], acc[i][j]);
            }
        }
        __syncthreads();
    }

    #pragma unroll
    for (int i = 0; i < 8; i++) {
        float o[8];
        #pragma unroll
        for (int j = 0; j < 4; j++) {
            float2 f = u2f(acc[i][j]);
            o[2 * j]     = f.x * alpha;
            o[2 * j + 1] = f.y * alpha;
        }
        float* crow = C + (size_t)(m0 + ty * 8 + i) * N + n0 + tx * 8;
        *(float4*)(crow)     = make_float4(o[0], o[1], o[2], o[3]);
        *(float4*)(crow + 4) = make_float4(o[4], o[5], o[6], o[7]);
    }
}

// ---------------------------------------------------------------------------
// Combine: attn = (1/8) * sum_h W_h / l_h   (memory-bound)
// ---------------------------------------------------------------------------
__global__ __launch_bounds__(256) void combine_kernel(float* __restrict__ attn)
{
    const int st = blockIdx.x, qt = blockIdx.y, b = blockIdx.z;
    const int tid = threadIdx.x;
    float* out = attn + (size_t)b * TT * TT;

    if (st > qt) {
        float4 z = make_float4(0.f, 0.f, 0.f, 0.f);
        #pragma unroll
        for (int r = 0; r < 16; r++) {
            int e = tid + r * 256;
            int i = e >> 5, j = (e & 31) << 2;
            *(float4*)(out + (size_t)(qt * 128 + i) * TT + st * 128 + j) = z;
        }
        return;
    }

    const int c  = (tid & 7) * 16;
    const int r0 = tid >> 3;

    for (int rr = 0; rr < 4; rr++) {
        const int r = r0 + rr * 32;
        const int t = qt * 128 + r;
        float acc[16];
        #pragma unroll
        for (int q = 0; q < 16; q++) acc[q] = 0.0f;

        #pragma unroll
        for (int h = 0; h < HH; h++) {
            float inv = 0.125f * __frcp_rn(g_L[(size_t)(b * HH + h) * TT + t]);
            const __half* sp = g_S + ((size_t)(b * HH + h) * TT + t) * TT + st * 128 + c;
            uint4 v0 = *(const uint4*)sp;
            uint4 v1 = *(const uint4*)(sp + 8);
            unsigned vs[8] = {v0.x, v0.y, v0.z, v0.w, v1.x, v1.y, v1.z, v1.w};
            #pragma unroll
            for (int p = 0; p < 8; p++) {
                float2 f = __half22float2(*(__half2*)&vs[p]);
                acc[2 * p]     = fmaf(f.x, inv, acc[2 * p]);
                acc[2 * p + 1] = fmaf(f.y, inv, acc[2 * p + 1]);
            }
        }
        float* orow = out + (size_t)t * TT + st * 128 + c;
        #pragma unroll
        for (int p = 0; p < 4; p++)
            *(float4*)(orow + 4 * p) =
                make_float4(acc[4 * p], acc[4 * p + 1], acc[4 * p + 2], acc[4 * p + 3]);
    }
}

// ---------------------------------------------------------------------------
extern "C" void kernel_launch(void* const* d_in, const int* in_sizes, int n_in,
                              void* d_out, int out_size)
{
    (void)in_sizes; (void)n_in; (void)out_size;
    const float* x  = (const float*)d_in[0];
    const float* Wq = (const float*)d_in[1];
    const float* Wk = (const float*)d_in[2];
    const float* Wv = (const float*)d_in[3];
    const float* Wo = (const float*)d_in[4];

    float* out  = (float*)d_out;                 // [B,T,U]
    float* attn = out + (size_t)BT * UU;         // [B,T,T]

    float *gq, *gk, *gv, *gop, *gwt;
    cudaGetSymbolAddress((void**)&gq,  g_Q);
    cudaGetSymbolAddress((void**)&gk,  g_K);
    cudaGetSymbolAddress((void**)&gv,  g_V);
    cudaGetSymbolAddress((void**)&gop, g_OP);
    cudaGetSymbolAddress((void**)&gwt, g_WT);

    const int SMEM_PROJ  = 2 * 4 * 128 * PITCH * 4;     // 48 KB
    const int SMEM_SCORE = 16 * 128 * PITCH * 4;        // 96 KB
    cudaFuncSetAttribute(mma_proj_kernel,  cudaFuncAttributeMaxDynamicSharedMemorySize, SMEM_PROJ);
    cudaFuncSetAttribute(mma_score_kernel, cudaFuncAttributeMaxDynamicSharedMemorySize, SMEM_SCORE);

    const float scale = 0.08838834764831845f;    // 1/sqrt(128)
    dim3 blk256(256);
    dim3 tgrid(UU / 32, UU / 32);
    dim3 tblk(32, 8);

    // Q projection (tensor core tf32, pre-scaled)
    transpose_kernel<<<tgrid, tblk>>>(Wq, gwt);
    mma_proj_kernel<<<dim3(UU / 128, BT / 128), blk256, SMEM_PROJ>>>(x, gwt, gq, scale);
    // K projection
    transpose_kernel<<<tgrid, tblk>>>(Wk, gwt);
    mma_proj_kernel<<<dim3(UU / 128, BT / 128), blk256, SMEM_PROJ>>>(x, gwt, gk, 1.0f);
    // V projection (small, FFMA2 path)
    sgemm_kernel<<<dim3(DD / 128, BT / 128, 1), blk256>>>(x, Wv, gv, BT, DD, UU, 1.0f, 0, 0, 0, 0);

    // Scores -> W (fp16) + l (tensor core tf32)
    mma_score_kernel<<<dim3(TT / 128, HH, BB), blk256, SMEM_SCORE>>>();

    // Combine heads -> attn (direct to output)
    combine_kernel<<<dim3(TT / 128, TT / 128, BB), blk256>>>(attn);

    // out_pre = attn @ v (batched, causal K-cap)
    sgemm_kernel<<<dim3(DD / 128, TT / 128, BB), blk256>>>(attn, gv, gop, TT, DD, TT, 1.0f,
                                                           (size_t)TT * TT, (size_t)TT * DD,
                                                           (size_t)TT * DD, 1);
    // out = out_pre @ Wo
    sgemm_kernel<<<dim3(UU / 128, BT / 128, 1), blk256>>>(gop, Wo, out, BT, UU, DD, 1.0f, 0, 0, 0, 0);
}

// round 14
// speedup vs baseline: 1.0019x; 1.0019x over previous
#include <cuda_runtime.h>
#include <cuda_fp16.h>
#include <math.h>
#include <stdint.h>

#define BB 4
#define TT 2048
#define UU 1024
#define HH 8
#define DD 128
#define BT (BB*TT)

typedef unsigned long long u64;

// Scratch (device globals per harness allocation rules)
static __device__ float  g_Q[BT*UU];                  // 33.5 MB (pre-scaled q)
static __device__ float  g_K[BT*UU];                  // 33.5 MB
static __device__ float  g_V[BT*DD];                  // 4.2 MB
static __device__ float  g_L[BB*HH*TT];               // row sum-exp per (b,h,t)
static __device__ float  g_OP[BT*DD];                 // attn @ v
static __device__ float  g_WT[UU*UU];                 // transposed weight buffer
static __device__ __half g_S[(size_t)BB*HH*TT*TT];    // 268 MB: W = exp(score), fp16

// ===================== mma.sync tf32 helpers (sm_80 path) ===================
__device__ __forceinline__ uint32_t smem_u32(const void* p) {
    uint32_t a;
    asm("{ .reg .u64 t; cvta.to.shared.u64 t, %1; cvt.u32.u64 %0, t; }" : "=r"(a) : "l"(p));
    return a;
}
__device__ __forceinline__ unsigned f2tf(float f) {
    unsigned u; asm("cvt.rna.tf32.f32 %0, %1;" : "=r"(u) : "f"(f)); return u;
}
__device__ __forceinline__ void mma8(float* c, const unsigned* a, const unsigned* b) {
    asm volatile("mma.sync.aligned.m16n8k8.row.col.f32.tf32.tf32.f32 "
        "{%0,%1,%2,%3}, {%4,%5,%6,%7}, {%8,%9}, {%0,%1,%2,%3};"
        : "+f"(c[0]), "+f"(c[1]), "+f"(c[2]), "+f"(c[3])
        : "r"(a[0]), "r"(a[1]), "r"(a[2]), "r"(a[3]), "r"(b[0]), "r"(b[1]));
}
__device__ __forceinline__ void ldsm4(unsigned* r, uint32_t addr) {
    asm volatile("ldmatrix.sync.aligned.m8n8.x4.shared.b16 {%0,%1,%2,%3}, [%4];"
        : "=r"(r[0]), "=r"(r[1]), "=r"(r[2]), "=r"(r[3]) : "r"(addr));
}

// Smem tile layout: [kc][row][12 floats] (8 used + 4 pad = 48B pitch).
// 48B pitch => ldmatrix 8-address phases hit 8 distinct 16B banks.
#define PITCH 12

// A-fragment ldmatrix address offsets (warp rows mrow0..mrow0+15):
//   lane<16: (row = mrow0 + lane,      col 0..3)
//   lane>=16:(row = mrow0 + lane - 16, col 4..7)
__device__ __forceinline__ uint32_t a_addr(uint32_t base, int kc, int mrow0, int lane) {
    int row = mrow0 + (lane & 15);
    int col = (lane >> 4) * 4;
    return base + (uint32_t)((kc * 128 + row) * PITCH + col) * 4u;
}
// B-fragment (x4 covers n-tiles n0 and n0+8):
//   lane 0-7:(n0+l, 0) 8-15:(n0+l-8, 4) 16-23:(n0+8+l-16, 0) 24-31:(n0+8+l-24, 4)
__device__ __forceinline__ uint32_t b_addr(uint32_t base, int kc, int n0, int lane) {
    int row = n0 + (lane & 7) + ((lane >> 4) << 3);
    int col = ((lane >> 3) & 1) * 4;
    return base + (uint32_t)((kc * 128 + row) * PITCH + col) * 4u;
}

// ---------------------------------------------------------------------------
// 32x32 transpose: WT[n][k] = W[k][n]  (UU x UU)
// ---------------------------------------------------------------------------
__global__ void transpose_kernel(const float* __restrict__ W, float* __restrict__ WT)
{
    __shared__ float t[32][33];
    int bx = blockIdx.x * 32, by = blockIdx.y * 32;
    #pragma unroll
    for (int i = 0; i < 32; i += 8)
        t[threadIdx.y + i][threadIdx.x] = W[(size_t)(by + threadIdx.y + i) * UU + bx + threadIdx.x];
    __syncthreads();
    #pragma unroll
    for (int i = 0; i < 32; i += 8)
        WT[(size_t)(bx + threadIdx.y + i) * UU + by + threadIdx.x] = t[threadIdx.x][threadIdx.y + i];
}

// ---------------------------------------------------------------------------
// tf32 mma.sync projection GEMM: C[M,N] = alpha * X[M,K] @ WT[N,K]^T
// Block 128x128, 8 warps (warp tile 16m x 128n), K-chunk 32.
// Grid (N/128, M/128). Dynamic smem: 2 * 4*128*48 = 48 KB.
// ---------------------------------------------------------------------------
__global__ __launch_bounds__(256, 2) void mma_proj_kernel(
    const float* __restrict__ X, const float* __restrict__ WT, float* __restrict__ C,
    float alpha)
{
    extern __shared__ float sm[];
    float* As = sm;                       // [4][128][12]
    float* Bs = sm + 4 * 128 * PITCH;     // [4][128][12]
    const uint32_t as_b = smem_u32(As), bs_b = smem_u32(Bs);

    const int tid = threadIdx.x;
    const int wid = tid >> 5, lane = tid & 31;
    const int n0 = blockIdx.x * 128, m0 = blockIdx.y * 128;
    const int mrow0 = wid * 16;

    float acc[16][4];
    #pragma unroll
    for (int j = 0; j < 16; j++)
        #pragma unroll
        for (int q = 0; q < 4; q++) acc[j][q] = 0.0f;

    for (int kb = 0; kb < UU; kb += 32) {
        // Stage A and B chunks (128 rows x 32 k) as tf32
        #pragma unroll
        for (int it = 0; it < 4; it++) {
            int idx = it * 256 + tid;          // 0..1023 float4s
            int r = idx >> 3;
            int kk = (idx & 7) * 4;
            int kc = kk >> 3, kin = kk & 7;
            float4 va = *(const float4*)(X + (size_t)(m0 + r) * UU + kb + kk);
            uint4 oa = make_uint4(f2tf(va.x), f2tf(va.y), f2tf(va.z), f2tf(va.w));
            *(uint4*)&As[(kc * 128 + r) * PITCH + kin] = oa;
            float4 vb = *(const float4*)(WT + (size_t)(n0 + r) * UU + kb + kk);
            uint4 ob = make_uint4(f2tf(vb.x), f2tf(vb.y), f2tf(vb.z), f2tf(vb.w));
            *(uint4*)&Bs[(kc * 128 + r) * PITCH + kin] = ob;
        }
        __syncthreads();

        #pragma unroll
        for (int kc = 0; kc < 4; kc++) {
            unsigned af[4];
            ldsm4(af, a_addr(as_b, kc, mrow0, lane));
            #pragma unroll
            for (int j = 0; j < 8; j++) {
                unsigned bf[4];
                ldsm4(bf, b_addr(bs_b, kc, j * 16, lane));
                mma8(acc[2 * j],     af, bf);
                mma8(acc[2 * j + 1], af, bf + 2);
            }
        }
        __syncthreads();
    }

    // Epilogue: c0,c1 -> (row=gid, col=j*8+2t, +1); c2,c3 -> row=gid+8
    const int gid = lane >> 2, tig = lane & 3;
    const int r0 = m0 + mrow0 + gid;
    #pragma unroll
    for (int j = 0; j < 16; j++) {
        int cc = n0 + j * 8 + 2 * tig;
        *(float2*)(C + (size_t)r0 * UU + cc) =
            make_float2(alpha * acc[j][0], alpha * acc[j][1]);
        *(float2*)(C + (size_t)(r0 + 8) * UU + cc) =
            make_float2(alpha * acc[j][2], alpha * acc[j][3]);
    }
}

// ---------------------------------------------------------------------------
// tf32 mma.sync score kernel: per (b, h, qt): scores vs all causal s-tiles,
// W = exp(score) -> fp16 g_S, row sums -> g_L.
// Q fragments live in registers (loaded once); K tiles stream through 96 KB smem.
// Grid (TT/128, HH, BB), 256 threads (8 warps x 16 rows).
// ---------------------------------------------------------------------------
__global__ __launch_bounds__(256, 1) void mma_score_kernel()
{
    extern __shared__ float sm[];                 // [16][128][12] = 96 KB
    const uint32_t sm_b = smem_u32(sm);

    const int tid = threadIdx.x;
    const int wid = tid >> 5, lane = tid & 31;
    const int qt = blockIdx.x, h = blockIdx.y, b = blockIdx.z;
    const int mrow0 = wid * 16;
    const int gid = lane >> 2, tig = lane & 3;

    const float* Qsrc  = g_Q + ((size_t)b * TT + (size_t)qt * 128) * UU + h * DD;
    const float* Kbase = g_K + (size_t)b * TT * UU + h * DD;
    __half* Sp = g_S + ((size_t)(b * HH + h) * TT + (size_t)qt * 128) * TT;

    // ---- Stage Q tile (128x128) and hoist fragments to registers ----
    #pragma unroll
    for (int it = 0; it < 16; it++) {
        int idx = it * 256 + tid;            // 0..4095 float4s
        int r = idx >> 5;
        int kk = (idx & 31) * 4;
        int kc = kk >> 3, kin = kk & 7;
        float4 v = *(const float4*)(Qsrc + (size_t)r * UU + kk);
        uint4 o = make_uint4(f2tf(v.x), f2tf(v.y), f2tf(v.z), f2tf(v.w));
        *(uint4*)&sm[(kc * 128 + r) * PITCH + kin] = o;
    }
    __syncthreads();

    unsigned qf[16][4];
    #pragma unroll
    for (int kc = 0; kc < 16; kc++)
        ldsm4(qf[kc], a_addr(sm_b, kc, mrow0, lane));
    __syncthreads();

    const int row0 = mrow0 + gid;            // local rows row0, row0+8
    const int t0 = qt * 128 + row0;
    float lsum0 = 0.0f, lsum1 = 0.0f;

    for (int st = 0; st <= qt; st++) {
        // Stage K tile (128 n x 128 k)
        #pragma unroll
        for (int it = 0; it < 16; it++) {
            int idx = it * 256 + tid;
            int r = idx >> 5;
            int kk = (idx & 31) * 4;
            int kc = kk >> 3, kin = kk & 7;
            float4 v = *(const float4*)(Kbase + (size_t)(st * 128 + r) * UU + kk);
            uint4 o = make_uint4(f2tf(v.x), f2tf(v.y), f2tf(v.z), f2tf(v.w));
            *(uint4*)&sm[(kc * 128 + r) * PITCH + kin] = o;
        }
        __syncthreads();

        float acc[16][4];
        #pragma unroll
        for (int j = 0; j < 16; j++)
            #pragma unroll
            for (int q = 0; q < 4; q++) acc[j][q] = 0.0f;

        #pragma unroll
        for (int kc = 0; kc < 16; kc++) {
            #pragma unroll
            for (int j = 0; j < 8; j++) {
                unsigned bf[4];
                ldsm4(bf, b_addr(sm_b, kc, j * 16, lane));
                mma8(acc[2 * j],     qf[kc], bf);
                mma8(acc[2 * j + 1], qf[kc], bf + 2);
            }
        }

        // Epilogue: mask diag, exp, accumulate l, store fp16
        const bool diag = (st == qt);
        __half* s0 = Sp + (size_t)row0 * TT + st * 128;
        __half* s1 = s0 + (size_t)8 * TT;
        #pragma unroll
        for (int j = 0; j < 16; j++) {
            int cc = j * 8 + 2 * tig;        // col within tile
            float w00 = (diag && (cc     > row0)) ? 0.0f : __expf(acc[j][0]);
            float w01 = (diag && (cc + 1 > row0)) ? 0.0f : __expf(acc[j][1]);
            float w10 = (diag && (cc     > row0 + 8)) ? 0.0f : __expf(acc[j][2]);
            float w11 = (diag && (cc + 1 > row0 + 8)) ? 0.0f : __expf(acc[j][3]);
            lsum0 += w00 + w01;
            lsum1 += w10 + w11;
            __half2 h0 = __floats2half2_rn(w00, w01);
            __half2 h1 = __floats2half2_rn(w10, w11);
            *(__half2*)(s0 + cc) = h0;
            *(__half2*)(s1 + cc) = h1;
        }
        __syncthreads();
    }

    // Row-sum reduce across the 4 lanes of each gid group (xor 1, 2)
    #pragma unroll
    for (int o = 1; o <= 2; o <<= 1) {
        lsum0 += __shfl_xor_sync(0xffffffffu, lsum0, o);
        lsum1 += __shfl_xor_sync(0xffffffffu, lsum1, o);
    }
    if (tig == 0) {
        size_t lb = (size_t)(b * HH + h) * TT;
        g_L[lb + t0]     = lsum0;
        g_L[lb + t0 + 8] = lsum1;
    }
}

// ---------------- f32x2 packed-FMA helpers (Blackwell FFMA2) ----------------
__device__ __forceinline__ u64 ffma2(u64 a, u64 b, u64 c) {
    u64 d;
    asm("fma.rn.f32x2 %0, %1, %2, %3;" : "=l"(d) : "l"(a), "l"(b), "l"(c));
    return d;
}
__device__ __forceinline__ u64 dup2(float x) {
    u64 r;
    asm("mov.b64 %0, {%1, %1};" : "=l"(r) : "f"(x));
    return r;
}
__device__ __forceinline__ float2 u2f(u64 v) {
    float2 f;
    asm("mov.b64 {%0, %1}, %2;" : "=f"(f.x), "=f"(f.y) : "l"(v));
    return f;
}

// ---------------------------------------------------------------------------
// fp32 GEMM with f32x2 math (small stages): C = alpha * A @ B
// ---------------------------------------------------------------------------
__global__ __launch_bounds__(256, 2) void sgemm_kernel(
    const float* __restrict__ A, const float* __restrict__ Bm, float* __restrict__ C,
    int M, int N, int K, float alpha,
    size_t sA, size_t sB, size_t sC, int causalK)
{
    A  += sA * blockIdx.z;
    Bm += sB * blockIdx.z;
    C  += sC * blockIdx.z;

    __shared__ __align__(16) float As[16][132];
    __shared__ __align__(16) float Bs[16][132];

    const int m0 = blockIdx.y * 128;
    const int n0 = blockIdx.x * 128;
    const int tid = threadIdx.x;
    const int ty = tid >> 4;
    const int tx = tid & 15;

    int Keff = causalK ? (int)(blockIdx.y + 1) * 128 : K;
    if (Keff > K) Keff = K;

    u64 acc[8][4];
    #pragma unroll
    for (int i = 0; i < 8; i++)
        #pragma unroll
        for (int j = 0; j < 4; j++) acc[i][j] = 0ull;

    for (int kt = 0; kt < Keff; kt += 16) {
        #pragma unroll
        for (int r = 0; r < 2; r++) {
            int e = tid + r * 256;
            int i = e >> 2, kk = (e & 3) << 2;
            float4 v = *(const float4*)(A + (size_t)(m0 + i) * K + kt + kk);
            As[kk + 0][i] = v.x; As[kk + 1][i] = v.y;
            As[kk + 2][i] = v.z; As[kk + 3][i] = v.w;
        }
        #pragma unroll
        for (int r = 0; r < 2; r++) {
            int e = tid + r * 256;
            int kk = e >> 5, j = (e & 31) << 2;
            *(float4*)&Bs[kk][j] = *(const float4*)(Bm + (size_t)(kt + kk) * N + n0 + j);
        }
        __syncthreads();

        #pragma unroll
        for (int k = 0; k < 16; k++) {
            float4 a0 = *(float4*)&As[k][ty * 8];
            float4 a1 = *(float4*)&As[k][ty * 8 + 4];
            ulonglong2 b0 = *(ulonglong2*)&Bs[k][tx * 8];
            ulonglong2 b1 = *(ulonglong2*)&Bs[k][tx * 8 + 4];
            u64 b[4] = {b0.x, b0.y, b1.x, b1.y};
            float av[8] = {a0.x, a0.y, a0.z, a0.w, a1.x, a1.y, a1.z, a1.w};
            #pragma unroll
            for (int i = 0; i < 8; i++) {
                u64 ad = dup2(av[i]);
                #pragma unroll
                for (int j = 0; j < 4; j++)
                    acc[i][j] = ffma2(ad, b[j], acc[i][j]);
            }
        }
        __syncthreads();
    }

    #pragma unroll
    for (int i = 0; i < 8; i++) {
        float o[8];
        #pragma unroll
        for (int j = 0; j < 4; j++) {
            float2 f = u2f(acc[i][j]);
            o[2 * j]     = f.x * alpha;
            o[2 * j + 1] = f.y * alpha;
        }
        float* crow = C + (size_t)(m0 + ty * 8 + i) * N + n0 + tx * 8;
        *(float4*)(crow)     = make_float4(o[0], o[1], o[2], o[3]);
        *(float4*)(crow + 4) = make_float4(o[4], o[5], o[6], o[7]);
    }
}

// ---------------------------------------------------------------------------
// Combine: attn = (1/8) * sum_h W_h / l_h   (memory-bound)
// ---------------------------------------------------------------------------
__global__ __launch_bounds__(256) void combine_kernel(float* __restrict__ attn)
{
    const int st = blockIdx.x, qt = blockIdx.y, b = blockIdx.z;
    const int tid = threadIdx.x;
    float* out = attn + (size_t)b * TT * TT;

    if (st > qt) {
        float4 z = make_float4(0.f, 0.f, 0.f, 0.f);
        #pragma unroll
        for (int r = 0; r < 16; r++) {
            int e = tid + r * 256;
            int i = e >> 5, j = (e & 31) << 2;
            *(float4*)(out + (size_t)(qt * 128 + i) * TT + st * 128 + j) = z;
        }
        return;
    }

    const int c  = (tid & 7) * 16;
    const int r0 = tid >> 3;

    for (int rr = 0; rr < 4; rr++) {
        const int r = r0 + rr * 32;
        const int t = qt * 128 + r;
        float acc[16];
        #pragma unroll
        for (int q = 0; q < 16; q++) acc[q] = 0.0f;

        #pragma unroll
        for (int h = 0; h < HH; h++) {
            float inv = 0.125f * __frcp_rn(g_L[(size_t)(b * HH + h) * TT + t]);
            const __half* sp = g_S + ((size_t)(b * HH + h) * TT + t) * TT + st * 128 + c;
            uint4 v0 = *(const uint4*)sp;
            uint4 v1 = *(const uint4*)(sp + 8);
            unsigned vs[8] = {v0.x, v0.y, v0.z, v0.w, v1.x, v1.y, v1.z, v1.w};
            #pragma unroll
            for (int p = 0; p < 8; p++) {
                float2 f = __half22float2(*(__half2*)&vs[p]);
                acc[2 * p]     = fmaf(f.x, inv, acc[2 * p]);
                acc[2 * p + 1] = fmaf(f.y, inv, acc[2 * p + 1]);
            }
        }
        float* orow = out + (size_t)t * TT + st * 128 + c;
        #pragma unroll
        for (int p = 0; p < 4; p++)
            *(float4*)(orow + 4 * p) =
                make_float4(acc[4 * p], acc[4 * p + 1], acc[4 * p + 2], acc[4 * p + 3]);
    }
}

// ---------------------------------------------------------------------------
extern "C" void kernel_launch(void* const* d_in, const int* in_sizes, int n_in,
                              void* d_out, int out_size)
{
    (void)in_sizes; (void)n_in; (void)out_size;
    const float* x  = (const float*)d_in[0];
    const float* Wq = (const float*)d_in[1];
    const float* Wk = (const float*)d_in[2];
    const float* Wv = (const float*)d_in[3];
    const float* Wo = (const float*)d_in[4];

    float* out  = (float*)d_out;                 // [B,T,U]
    float* attn = out + (size_t)BT * UU;         // [B,T,T]

    float *gq, *gk, *gv, *gop, *gwt;
    cudaGetSymbolAddress((void**)&gq,  g_Q);
    cudaGetSymbolAddress((void**)&gk,  g_K);
    cudaGetSymbolAddress((void**)&gv,  g_V);
    cudaGetSymbolAddress((void**)&gop, g_OP);
    cudaGetSymbolAddress((void**)&gwt, g_WT);

    const int SMEM_PROJ  = 2 * 4 * 128 * PITCH * 4;     // 48 KB
    const int SMEM_SCORE = 16 * 128 * PITCH * 4;        // 96 KB
    cudaFuncSetAttribute(mma_proj_kernel,  cudaFuncAttributeMaxDynamicSharedMemorySize, SMEM_PROJ);
    cudaFuncSetAttribute(mma_score_kernel, cudaFuncAttributeMaxDynamicSharedMemorySize, SMEM_SCORE);

    const float scale = 0.08838834764831845f;    // 1/sqrt(128)
    dim3 blk256(256);
    dim3 tgrid(UU / 32, UU / 32);
    dim3 tblk(32, 8);

    // Q projection (tensor core tf32, pre-scaled)
    transpose_kernel<<<tgrid, tblk>>>(Wq, gwt);
    mma_proj_kernel<<<dim3(UU / 128, BT / 128), blk256, SMEM_PROJ>>>(x, gwt, gq, scale);
    // K projection
    transpose_kernel<<<tgrid, tblk>>>(Wk, gwt);
    mma_proj_kernel<<<dim3(UU / 128, BT / 128), blk256, SMEM_PROJ>>>(x, gwt, gk, 1.0f);
    // V projection (small, FFMA2 path)
    sgemm_kernel<<<dim3(DD / 128, BT / 128, 1), blk256>>>(x, Wv, gv, BT, DD, UU, 1.0f, 0, 0, 0, 0);

    // Scores -> W (fp16) + l (tensor core tf32)
    mma_score_kernel<<<dim3(TT / 128, HH, BB), blk256, SMEM_SCORE>>>();

    // Combine heads -> attn (direct to output)
    combine_kernel<<<dim3(TT / 128, TT / 128, BB), blk256>>>(attn);

    // out_pre = attn @ v (batched, causal K-cap)
    sgemm_kernel<<<dim3(DD / 128, TT / 128, BB), blk256>>>(attn, gv, gop, TT, DD, TT, 1.0f,
                                                           (size_t)TT * TT, (size_t)TT * DD,
                                                           (size_t)TT * DD, 1);
    // out = out_pre @ Wo
    sgemm_kernel<<<dim3(UU / 128, BT / 128, 1), blk256>>>(gop, Wo, out, BT, UU, DD, 1.0f, 0, 0, 0, 0);
}